// round 9
// baseline (speedup 1.0000x reference)
#include <cuda_runtime.h>
#include <cstdint>

// GSHashEncoding: out[p,:] = concat(gather(code0, map0[p,:]), gather(code1, map1[p,:])) @ W
//   codes: [327680, 4] fp32  (level0 = first 65536 rows, level1 = next 262144 rows)
//   W:     [8, 48] fp32
//   map0:  [2097152, 4] int32 (indices into level0)
//   map1:  [2097152, 4] int32 (indices into level1)
//   out:   [2097152, 48] fp32

#define L0_SIZE   65536
#define RESO      2097152
#define NPB       256      // points per block
#define HALF      128      // staging half-tile (points)

__device__ __forceinline__ unsigned long long pack2(float lo, float hi) {
    unsigned long long r;
    asm("mov.b64 %0, {%1, %2};" : "=l"(r) : "f"(lo), "f"(hi));
    return r;
}
__device__ __forceinline__ void unpack2(unsigned long long v, float& lo, float& hi) {
    asm("mov.b64 {%0, %1}, %2;" : "=f"(lo), "=f"(hi) : "l"(v));
}
// d = a * b + d   (packed 2x fp32, Blackwell f32x2 pipe)
__device__ __forceinline__ void fma2(unsigned long long& d, unsigned long long a, unsigned long long b) {
    asm("fma.rn.f32x2 %0, %1, %2, %0;" : "+l"(d) : "l"(a), "l"(b));
}

__global__ void __launch_bounds__(256, 4) gshash_kernel(
    const float* __restrict__ codes,
    const float* __restrict__ W,
    const int*   __restrict__ map0,
    const int*   __restrict__ map1,
    float*       __restrict__ out)
{
    __shared__ float s_feats[NPB * 8];       // 8 KB: gathered features per point
    __shared__ float s_stage[HALF * 48];     // 24 KB: output staging (half tile)

    const int tid = threadIdx.x;
    const int g   = tid & 7;                 // column group: owns cols {g, g+8, ..., g+40}
    const long long pbase = (long long)blockIdx.x * NPB;

    // ---- W slice into registers, packed f32x2: pair j holds cols (g+16j, g+16j+8) ----
    unsigned long long w2[8][3];
#pragma unroll
    for (int k = 0; k < 8; k++) {
#pragma unroll
        for (int j = 0; j < 3; j++) {
            float lo = __ldg(W + k * 48 + g + 16 * j);
            float hi = __ldg(W + k * 48 + g + 16 * j + 8);
            w2[k][j] = pack2(lo, hi);
        }
    }

    // ---- Phase A: gather 8 features for one point per thread (8-wide MLP) ----
    {
        long long p = pbase + tid;
        int4 m0 = ((const int4*)map0)[p];
        int4 m1 = ((const int4*)map1)[p];
        const float* c1 = codes + (size_t)L0_SIZE * 4;
        float f[8];
        f[0] = __ldg(codes + (size_t)m0.x * 4 + 0);
        f[1] = __ldg(codes + (size_t)m0.y * 4 + 1);
        f[2] = __ldg(codes + (size_t)m0.z * 4 + 2);
        f[3] = __ldg(codes + (size_t)m0.w * 4 + 3);
        f[4] = __ldg(c1 + (size_t)m1.x * 4 + 0);
        f[5] = __ldg(c1 + (size_t)m1.y * 4 + 1);
        f[6] = __ldg(c1 + (size_t)m1.z * 4 + 2);
        f[7] = __ldg(c1 + (size_t)m1.w * 4 + 3);
#pragma unroll
        for (int k = 0; k < 8; k++) s_feats[tid * 8 + k] = f[k];
    }
    __syncthreads();

    // ---- Phase B: 8 threads per point (6 cols each), staged coalesced write-out ----
    const int slot = tid >> 3;               // 0..31 point slots per pass
#pragma unroll 1
    for (int h = 0; h < 2; h++) {
#pragma unroll
        for (int i = 0; i < 4; i++) {
            const int pl = h * HALF + i * 32 + slot;   // point index within block
            unsigned long long acc0 = 0ull, acc1 = 0ull, acc2v = 0ull;
#pragma unroll
            for (int k = 0; k < 8; k++) {
                float fv = s_feats[pl * 8 + k];        // broadcast-class LDS
                unsigned long long f2v = pack2(fv, fv);
                fma2(acc0,  f2v, w2[k][0]);
                fma2(acc1,  f2v, w2[k][1]);
                fma2(acc2v, f2v, w2[k][2]);
            }
            float* st = s_stage + (i * 32 + slot) * 48 + g;
            float lo, hi;
            unpack2(acc0,  lo, hi); st[0]  = lo; st[8]  = hi;
            unpack2(acc1,  lo, hi); st[16] = lo; st[24] = hi;
            unpack2(acc2v, lo, hi); st[32] = lo; st[40] = hi;
        }
        __syncthreads();
        // fully coalesced float4 copy-out of this half tile (128 pts * 48 f = 1536 float4)
        const float4* src = (const float4*)s_stage;
        float4* dst = (float4*)(out + (pbase + (long long)h * HALF) * 48);
#pragma unroll
        for (int i = 0; i < 6; i++)
            dst[tid + i * 256] = src[tid + i * 256];
        __syncthreads();
    }
}

extern "C" void kernel_launch(void* const* d_in, const int* in_sizes, int n_in,
                              void* d_out, int out_size) {
    const float* codes = (const float*)d_in[0];
    const float* W     = (const float*)d_in[1];
    const int*   map0  = (const int*)d_in[2];
    const int*   map1  = (const int*)d_in[3];
    float*       outp  = (float*)d_out;

    (void)in_sizes; (void)n_in; (void)out_size;
    gshash_kernel<<<RESO / NPB, 256>>>(codes, W, map0, map1, outp);
}